// round 14
// baseline (speedup 1.0000x reference)
#include <cuda_runtime.h>
#include <cstdint>

#define HW    65536
#define NQ    100
#define NT    32
#define NB    8
#define NROWP 112   // 7 mtiles * 16
#define NKT   4096  // k-tiles per batch (HW/16)
#define PBLK  64    // pixel blocks per batch in k_prep (1024 px each)

// ---------------- device scratch ----------------
__device__ uint4    g_bfrag[NB * NKT * 32 * 2];  // precomputed MMA B-fragments
__device__ float    g_tsumP[NB * PBLK * NT];     // per-block tsum partials
__device__ float    g_dotPM[NB * NROWP * NT];
__device__ float    g_dotSIG[NB * NROWP * NT];
__device__ float    g_sumSP[NB * NROWP];
__device__ float    g_sumSIG[NB * NROWP];
__device__ float    g_classT[NB * NT * NQ];      // [b][t][n]

// ---------------- helpers ----------------
__device__ __forceinline__ uint32_t pack_bf16(float hi, float lo) {
    uint32_t d;
    asm("cvt.rn.bf16x2.f32 %0, %1, %2;" : "=r"(d) : "f"(hi), "f"(lo));
    return d;
}

__device__ __forceinline__ void mma_bf16(float* c, const uint32_t* a,
                                         uint32_t b0, uint32_t b1) {
    asm volatile(
        "mma.sync.aligned.m16n8k16.row.col.f32.bf16.bf16.f32 "
        "{%0,%1,%2,%3}, {%4,%5,%6,%7}, {%8,%9}, {%0,%1,%2,%3};"
        : "+f"(c[0]), "+f"(c[1]), "+f"(c[2]), "+f"(c[3])
        : "r"(a[0]), "r"(a[1]), "r"(a[2]), "r"(a[3]), "r"(b0), "r"(b1));
}

__device__ __forceinline__ uint32_t fkey(float f) {
    uint32_t u = __float_as_uint(f);
    return (u & 0x80000000u) ? ~u : (u | 0x80000000u);
}
__device__ __forceinline__ float fkey_inv(uint32_t k) {
    uint32_t u = (k & 0x80000000u) ? (k ^ 0x80000000u) : ~k;
    return __uint_as_float(u);
}
__device__ __forceinline__ int sel4i(int a0, int a1, int a2, int a3, int s) {
    return s == 0 ? a0 : s == 1 ? a1 : s == 2 ? a2 : a3;
}

// ---------------- kernel 1 (fused prep): zero + class softmax + bits/bfrag ----
// grid (PBLK, NB), 256 threads. Per block: 1024 pixels (4 per thread).
// First 800 global warps additionally compute one (b,n) class-cost column.
__global__ __launch_bounds__(256) void k_prep(const float* __restrict__ tgt,
                                              const float* __restrict__ logits,
                                              const int* __restrict__ labels) {
    __shared__ uint32_t sbits[1024];
    __shared__ float    shcls[8][81];
    __shared__ float    stsum[NT];

    const int b = blockIdx.y, bx = blockIdx.x;
    const int tid = threadIdx.x, warp = tid >> 5, lane = tid & 31;
    const int gblk = b * PBLK + bx;            // 0..511

    // zero accumulators (disjoint slices; consumed only by later k_main)
    {
        int i = gblk * 256 + tid;              // 0..131071
        if (i < NB * NROWP * NT) { g_dotPM[i] = 0.f; g_dotSIG[i] = 0.f; }
        if (i < NB * NROWP)      { g_sumSP[i] = 0.f; g_sumSIG[i] = 0.f; }
    }
    if (tid < NT) stsum[tid] = 0.f;

    // class softmax on first 800 global warps
    int gw = gblk * 8 + warp;
    if (gw < NB * NQ) {
        int b2 = gw / NQ, n = gw - b2 * NQ;
        const float* L = logits + (size_t)(b2 * NQ + n) * 81;
        float x0 = L[lane];
        float x1 = (lane + 32 < 81) ? L[lane + 32] : -1e30f;
        float x2 = (lane + 64 < 81) ? L[lane + 64] : -1e30f;
        float m = fmaxf(x0, fmaxf(x1, x2));
        #pragma unroll
        for (int o = 16; o; o >>= 1) m = fmaxf(m, __shfl_xor_sync(0xffffffffu, m, o));
        float e0 = __expf(x0 - m);
        float e1 = (lane + 32 < 81) ? __expf(x1 - m) : 0.f;
        float e2 = (lane + 64 < 81) ? __expf(x2 - m) : 0.f;
        float s = e0 + e1 + e2;
        #pragma unroll
        for (int o = 16; o; o >>= 1) s += __shfl_xor_sync(0xffffffffu, s, o);
        shcls[warp][lane] = e0;
        if (lane + 32 < 81) shcls[warp][lane + 32] = e1;
        if (lane + 64 < 81) shcls[warp][lane + 64] = e2;
        __syncwarp();
        float inv = 1.0f / s;
        int lbl = labels[b2 * NT + lane];
        g_classT[(b2 * NT + lane) * NQ + n] = -shcls[warp][lbl] * inv;
    }

    // target-mask bits: 4 pixels per thread (two float4 source loads per target)
    int p0 = bx * 1024 + tid * 4;              // local pixel base (multiple of 4)
    int h = p0 >> 8, w = p0 & 255;
    size_t base = ((size_t)b * NT) * 262144 + (size_t)(2 * h) * 512 + 2 * w;
    uint32_t w0 = 0, w1 = 0, w2 = 0, w3 = 0;
    #pragma unroll
    for (int t = 0; t < 32; ++t) {
        float4 va = __ldcs((const float4*)(tgt + base + (size_t)t * 262144));
        float4 vb = __ldcs((const float4*)(tgt + base + (size_t)t * 262144 + 4));
        w0 |= (uint32_t)(va.x != 0.0f) << t;
        w1 |= (uint32_t)(va.z != 0.0f) << t;
        w2 |= (uint32_t)(vb.x != 0.0f) << t;
        w3 |= (uint32_t)(vb.z != 0.0f) << t;
    }
    *(uint4*)(sbits + tid * 4) = make_uint4(w0, w1, w2, w3);

    // per-warp tsum counts -> smem -> per-block partial write (no global atomics)
    __syncthreads();   // stsum zero visible; sbits complete for phase 2
    int cnt = 0;
    #pragma unroll
    for (int t = 0; t < 32; ++t) {
        unsigned m0 = __ballot_sync(0xffffffffu, (w0 >> t) & 1u);
        unsigned m1 = __ballot_sync(0xffffffffu, (w1 >> t) & 1u);
        unsigned m2 = __ballot_sync(0xffffffffu, (w2 >> t) & 1u);
        unsigned m3 = __ballot_sync(0xffffffffu, (w3 >> t) & 1u);
        if (lane == t) cnt = __popc(m0) + __popc(m1) + __popc(m2) + __popc(m3);
    }
    atomicAdd(&stsum[lane], (float)cnt);
    __syncthreads();
    if (tid < NT) g_tsumP[(b * PBLK + bx) * NT + tid] = stsum[tid];

    // B-fragment build: 64 ktiles per block, 8 per warp
    const int q4 = (lane & 3) << 2, rq = lane >> 2;
    #pragma unroll
    for (int i = 0; i < 8; ++i) {
        int ktl = warp * 8 + i;
        uint32_t t0 = sbits[ktl * 16 + q4]     >> rq;  // px 4q   -> k=2q
        uint32_t t1 = sbits[ktl * 16 + q4 + 1] >> rq;  // px 4q+1 -> k=2q+1
        uint32_t t2 = sbits[ktl * 16 + q4 + 2] >> rq;  // px 4q+2 -> k=2q+8
        uint32_t t3 = sbits[ktl * 16 + q4 + 3] >> rq;  // px 4q+3 -> k=2q+9
        uint4 lo, hi;
        lo.x = ((t0 & 1u) * 0x3F80u)         | ((t1 & 1u) * 0x3F800000u);
        lo.y = ((t2 & 1u) * 0x3F80u)         | ((t3 & 1u) * 0x3F800000u);
        lo.z = (((t0 >> 8) & 1u) * 0x3F80u)  | (((t1 >> 8) & 1u) * 0x3F800000u);
        lo.w = (((t2 >> 8) & 1u) * 0x3F80u)  | (((t3 >> 8) & 1u) * 0x3F800000u);
        hi.x = (((t0 >> 16) & 1u) * 0x3F80u) | (((t1 >> 16) & 1u) * 0x3F800000u);
        hi.y = (((t2 >> 16) & 1u) * 0x3F80u) | (((t3 >> 16) & 1u) * 0x3F800000u);
        hi.z = (((t0 >> 24) & 1u) * 0x3F80u) | (((t1 >> 24) & 1u) * 0x3F800000u);
        hi.w = (((t2 >> 24) & 1u) * 0x3F80u) | (((t3 >> 24) & 1u) * 0x3F800000u);
        int kt = bx * 64 + ktl;
        uint4* dst = g_bfrag + ((size_t)(b * NKT + kt) * 32 + lane) * 2;
        dst[0] = lo;
        dst[1] = hi;
    }
}

// ---------------- kernel 2: bf16x2 elementwise + MMA, float4 A-loads ---------
__global__ __launch_bounds__(256) void k_main(const float* __restrict__ pm) {
    __shared__ float sPM[16 * 32];
    __shared__ float sSG[16 * 32];
    __shared__ float sSP[16];
    __shared__ float sSS[16];

    const int b = blockIdx.z, mt = blockIdx.y;
    const int tid = threadIdx.x;
    const int warp = tid >> 5, lane = tid & 31;
    const int kstart = blockIdx.x * (HW / 8) + warp * (HW / 8 / 8);  // 1024 px/warp
    const int rq = lane >> 2;
    const int q4 = (lane & 3) << 2;
    const int kq = (lane & 3) << 1;
    const int r_lo = mt * 16 + rq, r_hi = r_lo + 8;
    const int rl = min(r_lo, NQ - 1), rh = min(r_hi, NQ - 1);

    for (int i = tid; i < 512; i += 256) { sPM[i] = 0.f; sSG[i] = 0.f; }
    if (tid < 16) { sSP[tid] = 0.f; sSS[tid] = 0.f; }
    __syncthreads();

    const float* pmb = pm + (size_t)b * NQ * HW;
    const uint4* bf  = g_bfrag + ((size_t)(b * NKT + (kstart >> 4)) * 32 + lane) * 2;

    const uint32_t HALF2  = 0x3F003F00u;
    const uint32_t NHALF2 = 0xBF00BF00u;
    const uint32_t ONES2  = 0x3F803F80u;

    float cpm[4][4], csg[4][4], csum[4];
    #pragma unroll
    for (int i = 0; i < 4; ++i) {
        csum[i] = 0.f;
        #pragma unroll
        for (int j = 0; j < 4; ++j) { cpm[i][j] = 0.f; csg[i][j] = 0.f; }
    }
    float splog0 = 0.f, splog1 = 0.f;

    #pragma unroll 4
    for (int it = 0; it < 64; ++it) {
        int k0 = kstart + it * 16 + q4;
        float4 xl = __ldcs((const float4*)(pmb + (size_t)rl * HW + k0));
        float4 xh = __ldcs((const float4*)(pmb + (size_t)rh * HW + k0));
        uint4 blo = bf[it * 64];
        uint4 bhi = bf[it * 64 + 1];

        uint32_t apm[4] = { pack_bf16(xl.y, xl.x), pack_bf16(xh.y, xh.x),
                            pack_bf16(xl.w, xl.z), pack_bf16(xh.w, xh.z) };

        uint32_t asg[4], aq[4];
        #pragma unroll
        for (int q = 0; q < 4; ++q) {
            uint32_t th;
            asm("mul.rn.bf16x2 %0, %1, %2;" : "=r"(th) : "r"(apm[q]), "r"(HALF2));
            asm("tanh.approx.bf16x2 %0, %1;" : "=r"(th) : "r"(th));
            asm("fma.rn.bf16x2 %0, %1, %2, %3;" : "=r"(asg[q]) : "r"(th), "r"(HALF2),  "r"(HALF2));
            asm("fma.rn.bf16x2 %0, %1, %2, %3;" : "=r"(aq[q])  : "r"(th), "r"(NHALF2), "r"(HALF2));
        }

        uint32_t prL, prH;
        asm("mul.rn.bf16x2 %0, %1, %2;" : "=r"(prL) : "r"(aq[0]), "r"(aq[2]));
        asm("mul.rn.bf16x2 %0, %1, %2;" : "=r"(prH) : "r"(aq[1]), "r"(aq[3]));
        float fL = __uint_as_float(prL << 16) * __uint_as_float(prL & 0xFFFF0000u);
        float fH = __uint_as_float(prH << 16) * __uint_as_float(prH & 0xFFFF0000u);
        splog0 += __logf(fL);
        splog1 += __logf(fH);

        mma_bf16(cpm[0], apm, blo.x, blo.y);
        mma_bf16(csg[0], asg, blo.x, blo.y);
        mma_bf16(cpm[1], apm, blo.z, blo.w);
        mma_bf16(csg[1], asg, blo.z, blo.w);
        mma_bf16(cpm[2], apm, bhi.x, bhi.y);
        mma_bf16(csg[2], asg, bhi.x, bhi.y);
        mma_bf16(cpm[3], apm, bhi.z, bhi.w);
        mma_bf16(csg[3], asg, bhi.z, bhi.w);
        mma_bf16(csum,   asg, ONES2, ONES2);
    }

    #pragma unroll
    for (int nt = 0; nt < 4; ++nt) {
        int c = nt * 8 + kq;
        atomicAdd(&sPM[rq * 32 + c],           cpm[nt][0]);
        atomicAdd(&sPM[rq * 32 + c + 1],       cpm[nt][1]);
        atomicAdd(&sPM[(rq + 8) * 32 + c],     cpm[nt][2]);
        atomicAdd(&sPM[(rq + 8) * 32 + c + 1], cpm[nt][3]);
        atomicAdd(&sSG[rq * 32 + c],           csg[nt][0]);
        atomicAdd(&sSG[rq * 32 + c + 1],       csg[nt][1]);
        atomicAdd(&sSG[(rq + 8) * 32 + c],     csg[nt][2]);
        atomicAdd(&sSG[(rq + 8) * 32 + c + 1], csg[nt][3]);
    }
    atomicAdd(&sSP[rq],     -splog0);
    atomicAdd(&sSP[rq + 8], -splog1);
    if (kq == 0) {
        atomicAdd(&sSS[rq],     csum[0]);
        atomicAdd(&sSS[rq + 8], csum[2]);
    }
    __syncthreads();

    for (int i = tid; i < 512; i += 256) {
        int r = i >> 5, c = i & 31;
        int grow = mt * 16 + r;
        atomicAdd(&g_dotPM[(b * NROWP + grow) * NT + c],  sPM[i]);
        atomicAdd(&g_dotSIG[(b * NROWP + grow) * NT + c], sSG[i]);
    }
    if (tid < 16) {
        int grow = mt * 16 + tid;
        atomicAdd(&g_sumSP[b * NROWP + grow],  sSP[tid]);
        atomicAdd(&g_sumSIG[b * NROWP + grow], sSS[tid]);
    }
}

// ---------------- kernel 3: cost assembly + branchless JV -------------------
__global__ __launch_bounds__(128) void k_hung(float* __restrict__ out) {
    const int b = blockIdx.x;
    const int tid = threadIdx.x;
    const int lane = tid & 31;
    __shared__ float CsBuf[NT * NQ + 40];
    __shared__ float u[NT + 1];
    __shared__ float ucol[NQ + 1];
    __shared__ int   psh[NQ + 1];
    __shared__ float tsums[NT];
    float* Cs = CsBuf + 1;

    // tsum from per-block partials (64 independent loads, coalesced over lanes)
    if (tid < NT) {
        float s = 0.f;
        #pragma unroll
        for (int p = 0; p < PBLK; ++p) s += g_tsumP[(b * PBLK + p) * NT + tid];
        tsums[tid] = s;
    }
    __syncthreads();

    for (int idx = tid; idx < NT * NQ; idx += 128) {
        int t = idx / NQ, n = idx - t * NQ;
        float spm  = g_sumSP[b * NROWP + n] * (1.0f / HW);
        float dpm  = g_dotPM[(b * NROWP + n) * NT + t] * (1.0f / HW);
        float dsg  = g_dotSIG[(b * NROWP + n) * NT + t];
        float den  = g_sumSIG[b * NROWP + n] + tsums[t] + 1.0f;
        float dice = 1.0f - __fdividef(2.0f * dsg + 1.0f, den);
        Cs[idx] = g_classT[b * NT * NQ + idx] + (spm - dpm) + dice;
    }
    for (int j = tid; j <= NQ; j += 128) psh[j] = 0;
    __syncthreads();
    if (tid >= 32) return;

    float v0 = 0.f, v1 = 0.f, v2 = 0.f, v3 = 0.f;
    int   p0 = 0, p1 = 0, p2 = 0, p3 = 0;
    int   w0 = 0, w1 = 0, w2 = 0, w3 = 0;

    // ---- greedy init ----
    uint32_t cm0 = 1u, cm1 = 0, cm2 = 0, cm3 = 0;
    uint32_t freerows = 0;
    for (int i = 1; i <= NT; ++i) {
        const float* Crow = Cs + (i - 1) * NQ;
        uint32_t k0 = (fkey(Crow[lane - 1]) & ~127u) | lane;
        k0 = (lane >= 1) ? k0 : 0xFFFFFFFFu;
        uint32_t k1 = (fkey(Crow[31 + lane]) & ~127u) | (32 + lane);
        uint32_t k2 = (fkey(Crow[63 + lane]) & ~127u) | (64 + lane);
        uint32_t k3 = (fkey(Crow[95 + lane]) & ~127u) | (96 + lane);
        k3 = (lane <= 4) ? k3 : 0xFFFFFFFFu;
        uint32_t bk = min(min(k0, k1), min(k2, k3));
        uint32_t kmin = __reduce_min_sync(0xffffffffu, bk);
        int js = kmin & 127;
        float ui = fkey_inv(kmin & ~127u);
        if (lane == 0) u[i] = ui;
        int slot = js >> 5;
        uint32_t bit = 1u << (js & 31);
        uint32_t cm = slot == 0 ? cm0 : slot == 1 ? cm1 : slot == 2 ? cm2 : cm3;
        if (!(cm & bit)) {
            if ((js & 31) == lane) {
                if (slot == 0) p0 = i; else if (slot == 1) p1 = i;
                else if (slot == 2) p2 = i; else p3 = i;
                psh[js] = i;
                ucol[js] = ui;
            }
            if (slot == 0) cm0 |= bit; else if (slot == 1) cm1 |= bit;
            else if (slot == 2) cm2 |= bit; else cm3 |= bit;
        } else {
            freerows |= 1u << (i - 1);
        }
    }
    __syncwarp();

    // ---- Dijkstra phases: branchless inner loop, lazy dual updates ----
    while (freerows) {
        int i = __ffs(freerows);
        freerows &= freerows - 1;
        float m0 = 1e30f, m1 = 1e30f, m2 = 1e30f, m3 = 1e30f;
        float dj0 = 0.f, dj1r = 0.f, dj2 = 0.f, dj3 = 0.f;
        float D = 0.f;
        unsigned usedm = 0;
        if (lane == 0) p0 = i;
        int j0 = 0, i0 = i;
        float ui0 = u[i];

        while (true) {
            unsigned joined = ((j0 & 31) == lane) ? (1u << (j0 >> 5)) : 0u;
            dj0  = (joined & 1u) ? D : dj0;
            dj1r = (joined & 2u) ? D : dj1r;
            dj2  = (joined & 4u) ? D : dj2;
            dj3  = (joined & 8u) ? D : dj3;
            usedm |= joined;

            const float* Cr = Cs + (i0 - 1) * NQ;
            float s0 = ui0 + v0, s1 = ui0 + v1, s2 = ui0 + v2, s3 = ui0 + v3;

            bool a0 = (lane >= 1) && !(usedm & 1u);
            bool a1 = !(usedm & 2u);
            bool a2 = !(usedm & 4u);
            bool a3 = (lane <= 4) && !(usedm & 8u);

            float c0 = Cr[lane - 1]  - s0;  c0 = a0 ? c0 : 1e30f;
            float c1 = Cr[31 + lane] - s1;  c1 = a1 ? c1 : 1e30f;
            float c2 = Cr[63 + lane] - s2;  c2 = a2 ? c2 : 1e30f;
            float c3 = Cr[95 + lane] - s3;  c3 = a3 ? c3 : 1e30f;

            bool b0 = c0 < m0; w0 = b0 ? j0 : w0; m0 = b0 ? c0 : m0;
            bool b1 = c1 < m1; w1 = b1 ? j0 : w1; m1 = b1 ? c1 : m1;
            bool b2 = c2 < m2; w2 = b2 ? j0 : w2; m2 = b2 ? c2 : m2;
            bool b3 = c3 < m3; w3 = b3 ? j0 : w3; m3 = b3 ? c3 : m3;

            uint32_t k0 = (fkey(m0) & ~127u) | lane;        k0 = a0 ? k0 : 0xFFFFFFFFu;
            uint32_t k1 = (fkey(m1) & ~127u) | (32 + lane); k1 = a1 ? k1 : 0xFFFFFFFFu;
            uint32_t k2 = (fkey(m2) & ~127u) | (64 + lane); k2 = a2 ? k2 : 0xFFFFFFFFu;
            uint32_t k3 = (fkey(m3) & ~127u) | (96 + lane); k3 = a3 ? k3 : 0xFFFFFFFFu;
            uint32_t bk = min(min(k0, k1), min(k2, k3));

            uint32_t kmin = __reduce_min_sync(0xffffffffu, bk);
            float delta = fkey_inv(kmin & ~127u);
            int j1 = kmin & 127;

            int   pj1 = psh[j1];
            float uc1 = ucol[j1];

            m0 -= (usedm & 1u) ? 0.f : delta;
            m1 -= (usedm & 2u) ? 0.f : delta;
            m2 -= (usedm & 4u) ? 0.f : delta;
            m3 -= (usedm & 8u) ? 0.f : delta;
            D += delta;

            j0 = j1;
            if (pj1 == 0) break;
            i0 = pj1;
            ui0 = uc1;
        }

        if (usedm & 1u) { float t = D - dj0;  v0 -= t; u[p0] += t; ucol[lane] += t; }
        if (usedm & 2u) { float t = D - dj1r; v1 -= t; u[p1] += t; ucol[32 + lane] += t; }
        if (usedm & 4u) { float t = D - dj2;  v2 -= t; u[p2] += t; ucol[64 + lane] += t; }
        if (usedm & 8u) { float t = D - dj3;  v3 -= t; u[p3] += t; ucol[96 + lane] += t; }
        __syncwarp();

        while (j0 != 0) {
            int j1  = __shfl_sync(0xffffffffu, sel4i(w0, w1, w2, w3, j0 >> 5), j0 & 31);
            int pj1 = (j1 == 0) ? i : psh[j1];
            if ((j0 & 31) == lane) {
                int s = j0 >> 5;
                if (s == 0) p0 = pj1; else if (s == 1) p1 = pj1;
                else if (s == 2) p2 = pj1; else p3 = pj1;
                psh[j0] = pj1;
                ucol[j0] = u[pj1];
            }
            j0 = j1;
            __syncwarp();
        }
        __syncwarp();
    }

    // parallel emit
    int base = 0;
    #pragma unroll
    for (int c = 0; c < 4; ++c) {
        int j = c * 32 + lane + 1;
        bool m = (j <= NQ) && (psh[j] != 0);
        unsigned ball = __ballot_sync(0xffffffffu, m);
        if (m) {
            int k = base + __popc(ball & ((1u << lane) - 1u));
            out[b * NT + k]           = (float)(j - 1);
            out[NB * NT + b * NT + k] = (float)(psh[j] - 1);
        }
        base += __popc(ball);
    }
}

// ---------------- launch ----------------
extern "C" void kernel_launch(void* const* d_in, const int* in_sizes, int n_in,
                              void* d_out, int out_size) {
    const float* logits = nullptr;
    const float* pmask  = nullptr;
    const float* tmask  = nullptr;
    const int*   labels = nullptr;

    for (int i = 0; i < n_in; ++i) {
        switch (in_sizes[i]) {
            case 64800:    logits = (const float*)d_in[i]; break;
            case 52428800: pmask  = (const float*)d_in[i]; break;
            case 256:      labels = (const int*)d_in[i];   break;
            default:
                if (in_sizes[i] == 67108864) tmask = (const float*)d_in[i];
                break;
        }
    }
    float* out = (float*)d_out;

    k_prep<<<dim3(PBLK, NB), 256>>>(tmask, logits, labels);
    k_main<<<dim3(8, 7, NB), 256>>>(pmask);
    k_hung<<<NB, 128>>>(out);
}

// round 15
// speedup vs baseline: 1.0713x; 1.0713x over previous
#include <cuda_runtime.h>
#include <cstdint>

#define HW    65536
#define NQ    100
#define NT    32
#define NB    8
#define NROWP 112   // 7 mtiles * 16
#define NKT   4096  // k-tiles per batch (HW/16)

// ---------------- device scratch ----------------
__device__ uint4    g_bfrag[NB * NKT * 32 * 2];  // precomputed MMA B-fragments
__device__ float    g_tsum[NB * NT];
__device__ float    g_dotPM[NB * NROWP * NT];
__device__ float    g_dotSIG[NB * NROWP * NT];
__device__ float    g_sumSP[NB * NROWP];
__device__ float    g_sumSIG[NB * NROWP];
__device__ float    g_classT[NB * NT * NQ];      // [b][t][n]

// ---------------- helpers ----------------
__device__ __forceinline__ uint32_t pack_bf16(float hi, float lo) {
    uint32_t d;
    asm("cvt.rn.bf16x2.f32 %0, %1, %2;" : "=r"(d) : "f"(hi), "f"(lo));
    return d;
}

__device__ __forceinline__ void mma_bf16(float* c, const uint32_t* a,
                                         uint32_t b0, uint32_t b1) {
    asm volatile(
        "mma.sync.aligned.m16n8k16.row.col.f32.bf16.bf16.f32 "
        "{%0,%1,%2,%3}, {%4,%5,%6,%7}, {%8,%9}, {%0,%1,%2,%3};"
        : "+f"(c[0]), "+f"(c[1]), "+f"(c[2]), "+f"(c[3])
        : "r"(a[0]), "r"(a[1]), "r"(a[2]), "r"(a[3]), "r"(b0), "r"(b1));
}

__device__ __forceinline__ uint32_t fkey(float f) {
    uint32_t u = __float_as_uint(f);
    return (u & 0x80000000u) ? ~u : (u | 0x80000000u);
}
__device__ __forceinline__ float fkey_inv(uint32_t k) {
    uint32_t u = (k & 0x80000000u) ? (k ^ 0x80000000u) : ~k;
    return __uint_as_float(u);
}
__device__ __forceinline__ int sel4i(int a0, int a1, int a2, int a3, int s) {
    return s == 0 ? a0 : s == 1 ? a1 : s == 2 ? a2 : a3;
}

// ---------------- kernel 1: class cost (+ accumulator zeroing) ----------------
__global__ void k_class(const float* __restrict__ logits,
                        const int* __restrict__ labels) {
    int gid = blockIdx.x * 32 + threadIdx.x;
    for (int i = gid; i < NB * NROWP * NT; i += NB * NQ * 32) {
        g_dotPM[i] = 0.f; g_dotSIG[i] = 0.f;
    }
    if (gid < NB * NROWP) { g_sumSP[gid] = 0.f; g_sumSIG[gid] = 0.f; }
    if (gid < NB * NT)    { g_tsum[gid] = 0.f; }

    int b = blockIdx.x / NQ, n = blockIdx.x % NQ;
    int lane = threadIdx.x;
    __shared__ float sh[81];
    const float* L = logits + (size_t)(b * NQ + n) * 81;

    float x0 = L[lane];
    float x1 = (lane + 32 < 81) ? L[lane + 32] : -1e30f;
    float x2 = (lane + 64 < 81) ? L[lane + 64] : -1e30f;
    float m = fmaxf(x0, fmaxf(x1, x2));
    #pragma unroll
    for (int o = 16; o; o >>= 1) m = fmaxf(m, __shfl_xor_sync(0xffffffffu, m, o));

    float e0 = __expf(x0 - m);
    float e1 = (lane + 32 < 81) ? __expf(x1 - m) : 0.f;
    float e2 = (lane + 64 < 81) ? __expf(x2 - m) : 0.f;
    float s = e0 + e1 + e2;
    #pragma unroll
    for (int o = 16; o; o >>= 1) s += __shfl_xor_sync(0xffffffffu, s, o);

    sh[lane] = e0;
    if (lane + 32 < 81) sh[lane + 32] = e1;
    if (lane + 64 < 81) sh[lane + 64] = e2;
    __syncwarp();

    float inv = 1.0f / s;
    int lbl = labels[b * NT + lane];
    g_classT[(b * NT + lane) * NQ + n] = -sh[lbl] * inv;
}

// ---------------- kernel 2: target masks -> sums + B-fragments ----------------
// 512 threads: group g (=tid>>8) loads targets 16g..16g+15 for its 2 pixels.
// Halves combined in shared -> full 32-bit pixel words. Halved per-thread load
// chain + doubled warps per block = ~2x memory-level parallelism.
__global__ __launch_bounds__(512) void k_tmask(const float* __restrict__ tgt) {
    __shared__ uint32_t slo[512];
    __shared__ uint32_t shi[512];
    const int b = blockIdx.y;
    const int tid = threadIdx.x;
    const int g = tid >> 8;               // target half
    const int px = tid & 255;             // pixel-pair slot
    const int lane = tid & 31;

    int p0 = blockIdx.x * 512 + px * 2;
    int h = p0 >> 8, w = p0 & 255;
    size_t base = ((size_t)(b * NT + g * 16)) * 262144 + (size_t)(2 * h) * 512 + 2 * w;
    uint32_t w0 = 0, w1 = 0;
    #pragma unroll
    for (int t = 0; t < 16; ++t) {
        float4 v = __ldcs((const float4*)(tgt + base + (size_t)t * 262144));
        w0 |= (uint32_t)(v.x != 0.0f) << (g * 16 + t);
        w1 |= (uint32_t)(v.z != 0.0f) << (g * 16 + t);
    }
    if (g == 0) { slo[px * 2] = w0; slo[px * 2 + 1] = w1; }
    else        { shi[px * 2] = w0; shi[px * 2 + 1] = w1; }
    __syncthreads();

    // combine halves + tsum ballots (warps 0..7 only; full warps, full masks)
    if (tid < 256) {
        uint32_t c0 = slo[tid * 2]     | shi[tid * 2];
        uint32_t c1 = slo[tid * 2 + 1] | shi[tid * 2 + 1];
        slo[tid * 2]     = c0;
        slo[tid * 2 + 1] = c1;
        int cnt = 0;
        #pragma unroll
        for (int t = 0; t < 32; ++t) {
            unsigned m0 = __ballot_sync(0xffffffffu, (c0 >> t) & 1u);
            unsigned m1 = __ballot_sync(0xffffffffu, (c1 >> t) & 1u);
            if (lane == t) cnt = __popc(m0) + __popc(m1);
        }
        atomicAdd(&g_tsum[b * NT + lane], (float)cnt);
    }
    __syncthreads();

    // B-fragment build: 16 warps x 2 ktiles (32 ktiles per block)
    const int warp = tid >> 5;
    const int q4 = (lane & 3) << 2, rq = lane >> 2;
    #pragma unroll
    for (int i = 0; i < 2; ++i) {
        int ktl = warp * 2 + i;
        uint32_t t0 = slo[ktl * 16 + q4]     >> rq;  // px 4q   -> k=2q
        uint32_t t1 = slo[ktl * 16 + q4 + 1] >> rq;  // px 4q+1 -> k=2q+1
        uint32_t t2 = slo[ktl * 16 + q4 + 2] >> rq;  // px 4q+2 -> k=2q+8
        uint32_t t3 = slo[ktl * 16 + q4 + 3] >> rq;  // px 4q+3 -> k=2q+9
        uint4 lo, hi;
        lo.x = ((t0 & 1u) * 0x3F80u)         | ((t1 & 1u) * 0x3F800000u);
        lo.y = ((t2 & 1u) * 0x3F80u)         | ((t3 & 1u) * 0x3F800000u);
        lo.z = (((t0 >> 8) & 1u) * 0x3F80u)  | (((t1 >> 8) & 1u) * 0x3F800000u);
        lo.w = (((t2 >> 8) & 1u) * 0x3F80u)  | (((t3 >> 8) & 1u) * 0x3F800000u);
        hi.x = (((t0 >> 16) & 1u) * 0x3F80u) | (((t1 >> 16) & 1u) * 0x3F800000u);
        hi.y = (((t2 >> 16) & 1u) * 0x3F80u) | (((t3 >> 16) & 1u) * 0x3F800000u);
        hi.z = (((t0 >> 24) & 1u) * 0x3F80u) | (((t1 >> 24) & 1u) * 0x3F800000u);
        hi.w = (((t2 >> 24) & 1u) * 0x3F80u) | (((t3 >> 24) & 1u) * 0x3F800000u);
        int kt = blockIdx.x * 32 + ktl;
        uint4* dst = g_bfrag + ((size_t)(b * NKT + kt) * 32 + lane) * 2;
        dst[0] = lo;
        dst[1] = hi;
    }
}

// ---------------- kernel 3: bf16x2 elementwise + MMA, float4 A-loads ---------
__global__ __launch_bounds__(256) void k_main(const float* __restrict__ pm) {
    __shared__ float sPM[16 * 32];
    __shared__ float sSG[16 * 32];
    __shared__ float sSP[16];
    __shared__ float sSS[16];

    const int b = blockIdx.z, mt = blockIdx.y;
    const int tid = threadIdx.x;
    const int warp = tid >> 5, lane = tid & 31;
    const int kstart = blockIdx.x * (HW / 8) + warp * (HW / 8 / 8);  // 1024 px/warp
    const int rq = lane >> 2;
    const int q4 = (lane & 3) << 2;
    const int kq = (lane & 3) << 1;
    const int r_lo = mt * 16 + rq, r_hi = r_lo + 8;
    const int rl = min(r_lo, NQ - 1), rh = min(r_hi, NQ - 1);

    for (int i = tid; i < 512; i += 256) { sPM[i] = 0.f; sSG[i] = 0.f; }
    if (tid < 16) { sSP[tid] = 0.f; sSS[tid] = 0.f; }
    __syncthreads();

    const float* pmb = pm + (size_t)b * NQ * HW;
    const uint4* bf  = g_bfrag + ((size_t)(b * NKT + (kstart >> 4)) * 32 + lane) * 2;

    const uint32_t HALF2  = 0x3F003F00u;
    const uint32_t NHALF2 = 0xBF00BF00u;
    const uint32_t ONES2  = 0x3F803F80u;

    float cpm[4][4], csg[4][4], csum[4];
    #pragma unroll
    for (int i = 0; i < 4; ++i) {
        csum[i] = 0.f;
        #pragma unroll
        for (int j = 0; j < 4; ++j) { cpm[i][j] = 0.f; csg[i][j] = 0.f; }
    }
    float splog0 = 0.f, splog1 = 0.f;

    #pragma unroll 4
    for (int it = 0; it < 64; ++it) {
        int k0 = kstart + it * 16 + q4;
        float4 xl = __ldcs((const float4*)(pmb + (size_t)rl * HW + k0));
        float4 xh = __ldcs((const float4*)(pmb + (size_t)rh * HW + k0));
        uint4 blo = bf[it * 64];
        uint4 bhi = bf[it * 64 + 1];

        uint32_t apm[4] = { pack_bf16(xl.y, xl.x), pack_bf16(xh.y, xh.x),
                            pack_bf16(xl.w, xl.z), pack_bf16(xh.w, xh.z) };

        uint32_t asg[4], aq[4];
        #pragma unroll
        for (int q = 0; q < 4; ++q) {
            uint32_t th;
            asm("mul.rn.bf16x2 %0, %1, %2;" : "=r"(th) : "r"(apm[q]), "r"(HALF2));
            asm("tanh.approx.bf16x2 %0, %1;" : "=r"(th) : "r"(th));
            asm("fma.rn.bf16x2 %0, %1, %2, %3;" : "=r"(asg[q]) : "r"(th), "r"(HALF2),  "r"(HALF2));
            asm("fma.rn.bf16x2 %0, %1, %2, %3;" : "=r"(aq[q])  : "r"(th), "r"(NHALF2), "r"(HALF2));
        }

        uint32_t prL, prH;
        asm("mul.rn.bf16x2 %0, %1, %2;" : "=r"(prL) : "r"(aq[0]), "r"(aq[2]));
        asm("mul.rn.bf16x2 %0, %1, %2;" : "=r"(prH) : "r"(aq[1]), "r"(aq[3]));
        float fL = __uint_as_float(prL << 16) * __uint_as_float(prL & 0xFFFF0000u);
        float fH = __uint_as_float(prH << 16) * __uint_as_float(prH & 0xFFFF0000u);
        splog0 += __logf(fL);
        splog1 += __logf(fH);

        mma_bf16(cpm[0], apm, blo.x, blo.y);
        mma_bf16(csg[0], asg, blo.x, blo.y);
        mma_bf16(cpm[1], apm, blo.z, blo.w);
        mma_bf16(csg[1], asg, blo.z, blo.w);
        mma_bf16(cpm[2], apm, bhi.x, bhi.y);
        mma_bf16(csg[2], asg, bhi.x, bhi.y);
        mma_bf16(cpm[3], apm, bhi.z, bhi.w);
        mma_bf16(csg[3], asg, bhi.z, bhi.w);
        mma_bf16(csum,   asg, ONES2, ONES2);
    }

    #pragma unroll
    for (int nt = 0; nt < 4; ++nt) {
        int c = nt * 8 + kq;
        atomicAdd(&sPM[rq * 32 + c],           cpm[nt][0]);
        atomicAdd(&sPM[rq * 32 + c + 1],       cpm[nt][1]);
        atomicAdd(&sPM[(rq + 8) * 32 + c],     cpm[nt][2]);
        atomicAdd(&sPM[(rq + 8) * 32 + c + 1], cpm[nt][3]);
        atomicAdd(&sSG[rq * 32 + c],           csg[nt][0]);
        atomicAdd(&sSG[rq * 32 + c + 1],       csg[nt][1]);
        atomicAdd(&sSG[(rq + 8) * 32 + c],     csg[nt][2]);
        atomicAdd(&sSG[(rq + 8) * 32 + c + 1], csg[nt][3]);
    }
    atomicAdd(&sSP[rq],     -splog0);
    atomicAdd(&sSP[rq + 8], -splog1);
    if (kq == 0) {
        atomicAdd(&sSS[rq],     csum[0]);
        atomicAdd(&sSS[rq + 8], csum[2]);
    }
    __syncthreads();

    for (int i = tid; i < 512; i += 256) {
        int r = i >> 5, c = i & 31;
        int grow = mt * 16 + r;
        atomicAdd(&g_dotPM[(b * NROWP + grow) * NT + c],  sPM[i]);
        atomicAdd(&g_dotSIG[(b * NROWP + grow) * NT + c], sSG[i]);
    }
    if (tid < 16) {
        int grow = mt * 16 + tid;
        atomicAdd(&g_sumSP[b * NROWP + grow],  sSP[tid]);
        atomicAdd(&g_sumSIG[b * NROWP + grow], sSS[tid]);
    }
}

// ---------------- kernel 4: cost assembly + branchless JV -------------------
__global__ __launch_bounds__(128) void k_hung(float* __restrict__ out) {
    const int b = blockIdx.x;
    const int tid = threadIdx.x;
    const int lane = tid & 31;
    __shared__ float CsBuf[NT * NQ + 40];
    __shared__ float u[NT + 1];
    __shared__ float ucol[NQ + 1];
    __shared__ int   psh[NQ + 1];
    float* Cs = CsBuf + 1;

    for (int idx = tid; idx < NT * NQ; idx += 128) {
        int t = idx / NQ, n = idx - t * NQ;
        float spm  = g_sumSP[b * NROWP + n] * (1.0f / HW);
        float dpm  = g_dotPM[(b * NROWP + n) * NT + t] * (1.0f / HW);
        float dsg  = g_dotSIG[(b * NROWP + n) * NT + t];
        float den  = g_sumSIG[b * NROWP + n] + g_tsum[b * NT + t] + 1.0f;
        float dice = 1.0f - __fdividef(2.0f * dsg + 1.0f, den);
        Cs[idx] = g_classT[b * NT * NQ + idx] + (spm - dpm) + dice;
    }
    for (int j = tid; j <= NQ; j += 128) psh[j] = 0;
    __syncthreads();
    if (tid >= 32) return;

    float v0 = 0.f, v1 = 0.f, v2 = 0.f, v3 = 0.f;
    int   p0 = 0, p1 = 0, p2 = 0, p3 = 0;
    int   w0 = 0, w1 = 0, w2 = 0, w3 = 0;

    // ---- greedy init ----
    uint32_t cm0 = 1u, cm1 = 0, cm2 = 0, cm3 = 0;
    uint32_t freerows = 0;
    for (int i = 1; i <= NT; ++i) {
        const float* Crow = Cs + (i - 1) * NQ;
        uint32_t k0 = (fkey(Crow[lane - 1]) & ~127u) | lane;
        k0 = (lane >= 1) ? k0 : 0xFFFFFFFFu;
        uint32_t k1 = (fkey(Crow[31 + lane]) & ~127u) | (32 + lane);
        uint32_t k2 = (fkey(Crow[63 + lane]) & ~127u) | (64 + lane);
        uint32_t k3 = (fkey(Crow[95 + lane]) & ~127u) | (96 + lane);
        k3 = (lane <= 4) ? k3 : 0xFFFFFFFFu;
        uint32_t bk = min(min(k0, k1), min(k2, k3));
        uint32_t kmin = __reduce_min_sync(0xffffffffu, bk);
        int js = kmin & 127;
        float ui = fkey_inv(kmin & ~127u);
        if (lane == 0) u[i] = ui;
        int slot = js >> 5;
        uint32_t bit = 1u << (js & 31);
        uint32_t cm = slot == 0 ? cm0 : slot == 1 ? cm1 : slot == 2 ? cm2 : cm3;
        if (!(cm & bit)) {
            if ((js & 31) == lane) {
                if (slot == 0) p0 = i; else if (slot == 1) p1 = i;
                else if (slot == 2) p2 = i; else p3 = i;
                psh[js] = i;
                ucol[js] = ui;
            }
            if (slot == 0) cm0 |= bit; else if (slot == 1) cm1 |= bit;
            else if (slot == 2) cm2 |= bit; else cm3 |= bit;
        } else {
            freerows |= 1u << (i - 1);
        }
    }
    __syncwarp();

    // ---- Dijkstra phases: branchless inner loop, lazy dual updates ----
    while (freerows) {
        int i = __ffs(freerows);
        freerows &= freerows - 1;
        float m0 = 1e30f, m1 = 1e30f, m2 = 1e30f, m3 = 1e30f;
        float dj0 = 0.f, dj1r = 0.f, dj2 = 0.f, dj3 = 0.f;
        float D = 0.f;
        unsigned usedm = 0;
        if (lane == 0) p0 = i;
        int j0 = 0, i0 = i;
        float ui0 = u[i];

        while (true) {
            unsigned joined = ((j0 & 31) == lane) ? (1u << (j0 >> 5)) : 0u;
            dj0  = (joined & 1u) ? D : dj0;
            dj1r = (joined & 2u) ? D : dj1r;
            dj2  = (joined & 4u) ? D : dj2;
            dj3  = (joined & 8u) ? D : dj3;
            usedm |= joined;

            const float* Cr = Cs + (i0 - 1) * NQ;
            float s0 = ui0 + v0, s1 = ui0 + v1, s2 = ui0 + v2, s3 = ui0 + v3;

            bool a0 = (lane >= 1) && !(usedm & 1u);
            bool a1 = !(usedm & 2u);
            bool a2 = !(usedm & 4u);
            bool a3 = (lane <= 4) && !(usedm & 8u);

            float c0 = Cr[lane - 1]  - s0;  c0 = a0 ? c0 : 1e30f;
            float c1 = Cr[31 + lane] - s1;  c1 = a1 ? c1 : 1e30f;
            float c2 = Cr[63 + lane] - s2;  c2 = a2 ? c2 : 1e30f;
            float c3 = Cr[95 + lane] - s3;  c3 = a3 ? c3 : 1e30f;

            bool b0 = c0 < m0; w0 = b0 ? j0 : w0; m0 = b0 ? c0 : m0;
            bool b1 = c1 < m1; w1 = b1 ? j0 : w1; m1 = b1 ? c1 : m1;
            bool b2 = c2 < m2; w2 = b2 ? j0 : w2; m2 = b2 ? c2 : m2;
            bool b3 = c3 < m3; w3 = b3 ? j0 : w3; m3 = b3 ? c3 : m3;

            uint32_t k0 = (fkey(m0) & ~127u) | lane;        k0 = a0 ? k0 : 0xFFFFFFFFu;
            uint32_t k1 = (fkey(m1) & ~127u) | (32 + lane); k1 = a1 ? k1 : 0xFFFFFFFFu;
            uint32_t k2 = (fkey(m2) & ~127u) | (64 + lane); k2 = a2 ? k2 : 0xFFFFFFFFu;
            uint32_t k3 = (fkey(m3) & ~127u) | (96 + lane); k3 = a3 ? k3 : 0xFFFFFFFFu;
            uint32_t bk = min(min(k0, k1), min(k2, k3));

            uint32_t kmin = __reduce_min_sync(0xffffffffu, bk);
            float delta = fkey_inv(kmin & ~127u);
            int j1 = kmin & 127;

            int   pj1 = psh[j1];
            float uc1 = ucol[j1];

            m0 -= (usedm & 1u) ? 0.f : delta;
            m1 -= (usedm & 2u) ? 0.f : delta;
            m2 -= (usedm & 4u) ? 0.f : delta;
            m3 -= (usedm & 8u) ? 0.f : delta;
            D += delta;

            j0 = j1;
            if (pj1 == 0) break;
            i0 = pj1;
            ui0 = uc1;
        }

        if (usedm & 1u) { float t = D - dj0;  v0 -= t; u[p0] += t; ucol[lane] += t; }
        if (usedm & 2u) { float t = D - dj1r; v1 -= t; u[p1] += t; ucol[32 + lane] += t; }
        if (usedm & 4u) { float t = D - dj2;  v2 -= t; u[p2] += t; ucol[64 + lane] += t; }
        if (usedm & 8u) { float t = D - dj3;  v3 -= t; u[p3] += t; ucol[96 + lane] += t; }
        __syncwarp();

        while (j0 != 0) {
            int j1  = __shfl_sync(0xffffffffu, sel4i(w0, w1, w2, w3, j0 >> 5), j0 & 31);
            int pj1 = (j1 == 0) ? i : psh[j1];
            if ((j0 & 31) == lane) {
                int s = j0 >> 5;
                if (s == 0) p0 = pj1; else if (s == 1) p1 = pj1;
                else if (s == 2) p2 = pj1; else p3 = pj1;
                psh[j0] = pj1;
                ucol[j0] = u[pj1];
            }
            j0 = j1;
            __syncwarp();
        }
        __syncwarp();
    }

    // parallel emit
    int base = 0;
    #pragma unroll
    for (int c = 0; c < 4; ++c) {
        int j = c * 32 + lane + 1;
        bool m = (j <= NQ) && (psh[j] != 0);
        unsigned ball = __ballot_sync(0xffffffffu, m);
        if (m) {
            int k = base + __popc(ball & ((1u << lane) - 1u));
            out[b * NT + k]           = (float)(j - 1);
            out[NB * NT + b * NT + k] = (float)(psh[j] - 1);
        }
        base += __popc(ball);
    }
}

// ---------------- launch ----------------
extern "C" void kernel_launch(void* const* d_in, const int* in_sizes, int n_in,
                              void* d_out, int out_size) {
    const float* logits = nullptr;
    const float* pmask  = nullptr;
    const float* tmask  = nullptr;
    const int*   labels = nullptr;

    for (int i = 0; i < n_in; ++i) {
        switch (in_sizes[i]) {
            case 64800:    logits = (const float*)d_in[i]; break;
            case 52428800: pmask  = (const float*)d_in[i]; break;
            case 256:      labels = (const int*)d_in[i];   break;
            default:
                if (in_sizes[i] == 67108864) tmask = (const float*)d_in[i];
                break;
        }
    }
    float* out = (float*)d_out;

    k_class<<<NB * NQ, 32>>>(logits, labels);
    k_tmask<<<dim3(HW / 512, NB), 512>>>(tmask);
    k_main<<<dim3(8, 7, NB), 256>>>(pmask);
    k_hung<<<NB, 128>>>(out);
}

// round 16
// speedup vs baseline: 1.1721x; 1.0941x over previous
#include <cuda_runtime.h>
#include <cstdint>

#define HW    65536
#define NQ    100
#define NT    32
#define NB    8
#define NROWP 112   // 7 mtiles * 16
#define NKT   4096  // k-tiles per batch (HW/16)

// ---------------- device scratch ----------------
__device__ unsigned short g_bcomp[NB * NKT * 32]; // 16-bit B-operand codes (2MB)
__device__ float    g_tsum[NB * NT];
__device__ float    g_dotPM[NB * NROWP * NT];
__device__ float    g_dotSIG[NB * NROWP * NT];
__device__ float    g_sumSP[NB * NROWP];
__device__ float    g_sumSIG[NB * NROWP];
__device__ float    g_classT[NB * NT * NQ];      // [b][t][n]

// ---------------- helpers ----------------
__device__ __forceinline__ uint32_t pack_bf16(float hi, float lo) {
    uint32_t d;
    asm("cvt.rn.bf16x2.f32 %0, %1, %2;" : "=r"(d) : "f"(hi), "f"(lo));
    return d;
}

__device__ __forceinline__ void mma_bf16(float* c, const uint32_t* a,
                                         uint32_t b0, uint32_t b1) {
    asm volatile(
        "mma.sync.aligned.m16n8k16.row.col.f32.bf16.bf16.f32 "
        "{%0,%1,%2,%3}, {%4,%5,%6,%7}, {%8,%9}, {%0,%1,%2,%3};"
        : "+f"(c[0]), "+f"(c[1]), "+f"(c[2]), "+f"(c[3])
        : "r"(a[0]), "r"(a[1]), "r"(a[2]), "r"(a[3]), "r"(b0), "r"(b1));
}

__device__ __forceinline__ uint32_t fkey(float f) {
    uint32_t u = __float_as_uint(f);
    return (u & 0x80000000u) ? ~u : (u | 0x80000000u);
}
__device__ __forceinline__ float fkey_inv(uint32_t k) {
    uint32_t u = (k & 0x80000000u) ? (k ^ 0x80000000u) : ~k;
    return __uint_as_float(u);
}
__device__ __forceinline__ int sel4i(int a0, int a1, int a2, int a3, int s) {
    return s == 0 ? a0 : s == 1 ? a1 : s == 2 ? a2 : a3;
}

// gather bits {0,8,16,24} of x into nibble [b0,b1,b2,b3] (carry-free multiply)
__device__ __forceinline__ uint32_t gath4(uint32_t x) {
    return (((x & 0x01010101u) * 0x01020408u) >> 24) & 0xFu;
}
// spread nibble bits j -> 4j (OR-based, carry-safe)
__device__ __forceinline__ uint32_t spr4(uint32_t n) {
    uint32_t a = (n | (n << 6)) & 0x0303u;
    return (a | (a << 3)) & 0x1111u;
}

// ---------------- kernel 1: class cost (+ accumulator zeroing) ----------------
__global__ void k_class(const float* __restrict__ logits,
                        const int* __restrict__ labels) {
    int gid = blockIdx.x * 32 + threadIdx.x;
    for (int i = gid; i < NB * NROWP * NT; i += NB * NQ * 32) {
        g_dotPM[i] = 0.f; g_dotSIG[i] = 0.f;
    }
    if (gid < NB * NROWP) { g_sumSP[gid] = 0.f; g_sumSIG[gid] = 0.f; }
    if (gid < NB * NT)    { g_tsum[gid] = 0.f; }

    int b = blockIdx.x / NQ, n = blockIdx.x % NQ;
    int lane = threadIdx.x;
    __shared__ float sh[81];
    const float* L = logits + (size_t)(b * NQ + n) * 81;

    float x0 = L[lane];
    float x1 = (lane + 32 < 81) ? L[lane + 32] : -1e30f;
    float x2 = (lane + 64 < 81) ? L[lane + 64] : -1e30f;
    float m = fmaxf(x0, fmaxf(x1, x2));
    #pragma unroll
    for (int o = 16; o; o >>= 1) m = fmaxf(m, __shfl_xor_sync(0xffffffffu, m, o));

    float e0 = __expf(x0 - m);
    float e1 = (lane + 32 < 81) ? __expf(x1 - m) : 0.f;
    float e2 = (lane + 64 < 81) ? __expf(x2 - m) : 0.f;
    float s = e0 + e1 + e2;
    #pragma unroll
    for (int o = 16; o; o >>= 1) s += __shfl_xor_sync(0xffffffffu, s, o);

    sh[lane] = e0;
    if (lane + 32 < 81) sh[lane + 32] = e1;
    if (lane + 64 < 81) sh[lane + 64] = e2;
    __syncwarp();

    float inv = 1.0f / s;
    int lbl = labels[b * NT + lane];
    g_classT[(b * NT + lane) * NQ + n] = -sh[lbl] * inv;
}

// ---------------- kernel 2: target masks -> sums + compact B codes ----------
__global__ __launch_bounds__(512) void k_tmask(const float* __restrict__ tgt) {
    __shared__ uint32_t slo[512];
    __shared__ uint32_t shi[512];
    const int b = blockIdx.y;
    const int tid = threadIdx.x;
    const int g = tid >> 8;               // target half
    const int px = tid & 255;             // pixel-pair slot
    const int lane = tid & 31;

    int p0 = blockIdx.x * 512 + px * 2;
    int h = p0 >> 8, w = p0 & 255;
    size_t base = ((size_t)(b * NT + g * 16)) * 262144 + (size_t)(2 * h) * 512 + 2 * w;
    uint32_t w0 = 0, w1 = 0;
    #pragma unroll
    for (int t = 0; t < 16; ++t) {
        float4 v = __ldcs((const float4*)(tgt + base + (size_t)t * 262144));
        w0 |= (uint32_t)(v.x != 0.0f) << (g * 16 + t);
        w1 |= (uint32_t)(v.z != 0.0f) << (g * 16 + t);
    }
    if (g == 0) { slo[px * 2] = w0; slo[px * 2 + 1] = w1; }
    else        { shi[px * 2] = w0; shi[px * 2 + 1] = w1; }
    __syncthreads();

    if (tid < 256) {
        uint32_t c0 = slo[tid * 2]     | shi[tid * 2];
        uint32_t c1 = slo[tid * 2 + 1] | shi[tid * 2 + 1];
        slo[tid * 2]     = c0;
        slo[tid * 2 + 1] = c1;
        int cnt = 0;
        #pragma unroll
        for (int t = 0; t < 32; ++t) {
            unsigned m0 = __ballot_sync(0xffffffffu, (c0 >> t) & 1u);
            unsigned m1 = __ballot_sync(0xffffffffu, (c1 >> t) & 1u);
            if (lane == t) cnt = __popc(m0) + __popc(m1);
        }
        atomicAdd(&g_tsum[b * NT + lane], (float)cnt);
    }
    __syncthreads();

    // compact B-code build: 16 warps x 2 ktiles (32 ktiles per block)
    const int warp = tid >> 5;
    const int q4 = (lane & 3) << 2, rq = lane >> 2;
    #pragma unroll
    for (int i = 0; i < 2; ++i) {
        int ktl = warp * 2 + i;
        uint32_t t0 = slo[ktl * 16 + q4]     >> rq;  // px 4q   -> k=2q
        uint32_t t1 = slo[ktl * 16 + q4 + 1] >> rq;  // px 4q+1 -> k=2q+1
        uint32_t t2 = slo[ktl * 16 + q4 + 2] >> rq;  // px 4q+2 -> k=2q+8
        uint32_t t3 = slo[ktl * 16 + q4 + 3] >> rq;  // px 4q+3 -> k=2q+9
        // b16 bit (4*nt + i) = t_i bit (8*nt)
        uint32_t b16 = spr4(gath4(t0)) | (spr4(gath4(t1)) << 1)
                     | (spr4(gath4(t2)) << 2) | (spr4(gath4(t3)) << 3);
        int kt = blockIdx.x * 32 + ktl;
        g_bcomp[(size_t)(b * NKT + kt) * 32 + lane] = (unsigned short)b16;
    }
}

// ---------------- kernel 3: bf16x2 elementwise + MMA, compact-B expand ------
__global__ __launch_bounds__(256) void k_main(const float* __restrict__ pm) {
    __shared__ float sPM[16 * 32];
    __shared__ float sSG[16 * 32];
    __shared__ float sSP[16];
    __shared__ float sSS[16];

    const int b = blockIdx.z, mt = blockIdx.y;
    const int tid = threadIdx.x;
    const int warp = tid >> 5, lane = tid & 31;
    const int kstart = blockIdx.x * (HW / 8) + warp * (HW / 8 / 8);  // 1024 px/warp
    const int rq = lane >> 2;
    const int q4 = (lane & 3) << 2;
    const int kq = (lane & 3) << 1;
    const int r_lo = mt * 16 + rq, r_hi = r_lo + 8;
    const int rl = min(r_lo, NQ - 1), rh = min(r_hi, NQ - 1);

    for (int i = tid; i < 512; i += 256) { sPM[i] = 0.f; sSG[i] = 0.f; }
    if (tid < 16) { sSP[tid] = 0.f; sSS[tid] = 0.f; }
    __syncthreads();

    const float* pmb = pm + (size_t)b * NQ * HW;
    const unsigned short* bc = g_bcomp + (size_t)(b * NKT + (kstart >> 4)) * 32 + lane;

    const uint32_t HALF2  = 0x3F003F00u;
    const uint32_t NHALF2 = 0xBF00BF00u;
    const uint32_t ONES2  = 0x3F803F80u;

    float cpm[4][4], csg[4][4], csum[4];
    #pragma unroll
    for (int i = 0; i < 4; ++i) {
        csum[i] = 0.f;
        #pragma unroll
        for (int j = 0; j < 4; ++j) { cpm[i][j] = 0.f; csg[i][j] = 0.f; }
    }
    float splog0 = 0.f, splog1 = 0.f;

    #pragma unroll 4
    for (int it = 0; it < 64; ++it) {
        int k0 = kstart + it * 16 + q4;
        float4 xl = __ldcs((const float4*)(pmb + (size_t)rl * HW + k0));
        float4 xh = __ldcs((const float4*)(pmb + (size_t)rh * HW + k0));
        uint32_t b16 = bc[it * 32];

        uint32_t apm[4] = { pack_bf16(xl.y, xl.x), pack_bf16(xh.y, xh.x),
                            pack_bf16(xl.w, xl.z), pack_bf16(xh.w, xh.z) };

        uint32_t asg[4], aq[4];
        #pragma unroll
        for (int q = 0; q < 4; ++q) {
            uint32_t th;
            asm("mul.rn.bf16x2 %0, %1, %2;" : "=r"(th) : "r"(apm[q]), "r"(HALF2));
            asm("tanh.approx.bf16x2 %0, %1;" : "=r"(th) : "r"(th));
            asm("fma.rn.bf16x2 %0, %1, %2, %3;" : "=r"(asg[q]) : "r"(th), "r"(HALF2),  "r"(HALF2));
            asm("fma.rn.bf16x2 %0, %1, %2, %3;" : "=r"(aq[q])  : "r"(th), "r"(NHALF2), "r"(HALF2));
        }

        uint32_t prL, prH;
        asm("mul.rn.bf16x2 %0, %1, %2;" : "=r"(prL) : "r"(aq[0]), "r"(aq[2]));
        asm("mul.rn.bf16x2 %0, %1, %2;" : "=r"(prH) : "r"(aq[1]), "r"(aq[3]));
        float fL = __uint_as_float(prL << 16) * __uint_as_float(prL & 0xFFFF0000u);
        float fH = __uint_as_float(prH << 16) * __uint_as_float(prH & 0xFFFF0000u);
        splog0 += __logf(fL);
        splog1 += __logf(fH);

        #pragma unroll
        for (int nt = 0; nt < 4; ++nt) {
            uint32_t nib = (b16 >> (4 * nt)) & 0xFu;
            uint32_t bO0 = (nib & 1u) * 0x3F80u | ((nib >> 1) & 1u) * 0x3F800000u;
            uint32_t bO1 = ((nib >> 2) & 1u) * 0x3F80u | ((nib >> 3) & 1u) * 0x3F800000u;
            mma_bf16(cpm[nt], apm, bO0, bO1);
            mma_bf16(csg[nt], asg, bO0, bO1);
        }
        mma_bf16(csum, asg, ONES2, ONES2);
    }

    #pragma unroll
    for (int nt = 0; nt < 4; ++nt) {
        int c = nt * 8 + kq;
        atomicAdd(&sPM[rq * 32 + c],           cpm[nt][0]);
        atomicAdd(&sPM[rq * 32 + c + 1],       cpm[nt][1]);
        atomicAdd(&sPM[(rq + 8) * 32 + c],     cpm[nt][2]);
        atomicAdd(&sPM[(rq + 8) * 32 + c + 1], cpm[nt][3]);
        atomicAdd(&sSG[rq * 32 + c],           csg[nt][0]);
        atomicAdd(&sSG[rq * 32 + c + 1],       csg[nt][1]);
        atomicAdd(&sSG[(rq + 8) * 32 + c],     csg[nt][2]);
        atomicAdd(&sSG[(rq + 8) * 32 + c + 1], csg[nt][3]);
    }
    atomicAdd(&sSP[rq],     -splog0);
    atomicAdd(&sSP[rq + 8], -splog1);
    if (kq == 0) {
        atomicAdd(&sSS[rq],     csum[0]);
        atomicAdd(&sSS[rq + 8], csum[2]);
    }
    __syncthreads();

    for (int i = tid; i < 512; i += 256) {
        int r = i >> 5, c = i & 31;
        int grow = mt * 16 + r;
        atomicAdd(&g_dotPM[(b * NROWP + grow) * NT + c],  sPM[i]);
        atomicAdd(&g_dotSIG[(b * NROWP + grow) * NT + c], sSG[i]);
    }
    if (tid < 16) {
        int grow = mt * 16 + tid;
        atomicAdd(&g_sumSP[b * NROWP + grow],  sSP[tid]);
        atomicAdd(&g_sumSIG[b * NROWP + grow], sSS[tid]);
    }
}

// ---------------- kernel 4: cost assembly + branchless JV -------------------
__global__ __launch_bounds__(128) void k_hung(float* __restrict__ out) {
    const int b = blockIdx.x;
    const int tid = threadIdx.x;
    const int lane = tid & 31;
    __shared__ float CsBuf[NT * NQ + 40];
    __shared__ float u[NT + 1];
    __shared__ float ucol[NQ + 1];
    __shared__ int   psh[NQ + 1];
    float* Cs = CsBuf + 1;

    for (int idx = tid; idx < NT * NQ; idx += 128) {
        int t = idx / NQ, n = idx - t * NQ;
        float spm  = g_sumSP[b * NROWP + n] * (1.0f / HW);
        float dpm  = g_dotPM[(b * NROWP + n) * NT + t] * (1.0f / HW);
        float dsg  = g_dotSIG[(b * NROWP + n) * NT + t];
        float den  = g_sumSIG[b * NROWP + n] + g_tsum[b * NT + t] + 1.0f;
        float dice = 1.0f - __fdividef(2.0f * dsg + 1.0f, den);
        Cs[idx] = g_classT[b * NT * NQ + idx] + (spm - dpm) + dice;
    }
    for (int j = tid; j <= NQ; j += 128) psh[j] = 0;
    __syncthreads();
    if (tid >= 32) return;

    float v0 = 0.f, v1 = 0.f, v2 = 0.f, v3 = 0.f;
    int   p0 = 0, p1 = 0, p2 = 0, p3 = 0;
    int   w0 = 0, w1 = 0, w2 = 0, w3 = 0;

    // ---- greedy init ----
    uint32_t cm0 = 1u, cm1 = 0, cm2 = 0, cm3 = 0;
    uint32_t freerows = 0;
    for (int i = 1; i <= NT; ++i) {
        const float* Crow = Cs + (i - 1) * NQ;
        uint32_t k0 = (fkey(Crow[lane - 1]) & ~127u) | lane;
        k0 = (lane >= 1) ? k0 : 0xFFFFFFFFu;
        uint32_t k1 = (fkey(Crow[31 + lane]) & ~127u) | (32 + lane);
        uint32_t k2 = (fkey(Crow[63 + lane]) & ~127u) | (64 + lane);
        uint32_t k3 = (fkey(Crow[95 + lane]) & ~127u) | (96 + lane);
        k3 = (lane <= 4) ? k3 : 0xFFFFFFFFu;
        uint32_t bk = min(min(k0, k1), min(k2, k3));
        uint32_t kmin = __reduce_min_sync(0xffffffffu, bk);
        int js = kmin & 127;
        float ui = fkey_inv(kmin & ~127u);
        if (lane == 0) u[i] = ui;
        int slot = js >> 5;
        uint32_t bit = 1u << (js & 31);
        uint32_t cm = slot == 0 ? cm0 : slot == 1 ? cm1 : slot == 2 ? cm2 : cm3;
        if (!(cm & bit)) {
            if ((js & 31) == lane) {
                if (slot == 0) p0 = i; else if (slot == 1) p1 = i;
                else if (slot == 2) p2 = i; else p3 = i;
                psh[js] = i;
                ucol[js] = ui;
            }
            if (slot == 0) cm0 |= bit; else if (slot == 1) cm1 |= bit;
            else if (slot == 2) cm2 |= bit; else cm3 |= bit;
        } else {
            freerows |= 1u << (i - 1);
        }
    }
    __syncwarp();

    // ---- Dijkstra phases: branchless inner loop, lazy dual updates ----
    while (freerows) {
        int i = __ffs(freerows);
        freerows &= freerows - 1;
        float m0 = 1e30f, m1 = 1e30f, m2 = 1e30f, m3 = 1e30f;
        float dj0 = 0.f, dj1r = 0.f, dj2 = 0.f, dj3 = 0.f;
        float D = 0.f;
        unsigned usedm = 0;
        if (lane == 0) p0 = i;
        int j0 = 0, i0 = i;
        float ui0 = u[i];

        while (true) {
            unsigned joined = ((j0 & 31) == lane) ? (1u << (j0 >> 5)) : 0u;
            dj0  = (joined & 1u) ? D : dj0;
            dj1r = (joined & 2u) ? D : dj1r;
            dj2  = (joined & 4u) ? D : dj2;
            dj3  = (joined & 8u) ? D : dj3;
            usedm |= joined;

            const float* Cr = Cs + (i0 - 1) * NQ;
            float s0 = ui0 + v0, s1 = ui0 + v1, s2 = ui0 + v2, s3 = ui0 + v3;

            bool a0 = (lane >= 1) && !(usedm & 1u);
            bool a1 = !(usedm & 2u);
            bool a2 = !(usedm & 4u);
            bool a3 = (lane <= 4) && !(usedm & 8u);

            float c0 = Cr[lane - 1]  - s0;  c0 = a0 ? c0 : 1e30f;
            float c1 = Cr[31 + lane] - s1;  c1 = a1 ? c1 : 1e30f;
            float c2 = Cr[63 + lane] - s2;  c2 = a2 ? c2 : 1e30f;
            float c3 = Cr[95 + lane] - s3;  c3 = a3 ? c3 : 1e30f;

            bool b0 = c0 < m0; w0 = b0 ? j0 : w0; m0 = b0 ? c0 : m0;
            bool b1 = c1 < m1; w1 = b1 ? j0 : w1; m1 = b1 ? c1 : m1;
            bool b2 = c2 < m2; w2 = b2 ? j0 : w2; m2 = b2 ? c2 : m2;
            bool b3 = c3 < m3; w3 = b3 ? j0 : w3; m3 = b3 ? c3 : m3;

            uint32_t k0 = (fkey(m0) & ~127u) | lane;        k0 = a0 ? k0 : 0xFFFFFFFFu;
            uint32_t k1 = (fkey(m1) & ~127u) | (32 + lane); k1 = a1 ? k1 : 0xFFFFFFFFu;
            uint32_t k2 = (fkey(m2) & ~127u) | (64 + lane); k2 = a2 ? k2 : 0xFFFFFFFFu;
            uint32_t k3 = (fkey(m3) & ~127u) | (96 + lane); k3 = a3 ? k3 : 0xFFFFFFFFu;
            uint32_t bk = min(min(k0, k1), min(k2, k3));

            uint32_t kmin = __reduce_min_sync(0xffffffffu, bk);
            float delta = fkey_inv(kmin & ~127u);
            int j1 = kmin & 127;

            int   pj1 = psh[j1];
            float uc1 = ucol[j1];

            m0 -= (usedm & 1u) ? 0.f : delta;
            m1 -= (usedm & 2u) ? 0.f : delta;
            m2 -= (usedm & 4u) ? 0.f : delta;
            m3 -= (usedm & 8u) ? 0.f : delta;
            D += delta;

            j0 = j1;
            if (pj1 == 0) break;
            i0 = pj1;
            ui0 = uc1;
        }

        if (usedm & 1u) { float t = D - dj0;  v0 -= t; u[p0] += t; ucol[lane] += t; }
        if (usedm & 2u) { float t = D - dj1r; v1 -= t; u[p1] += t; ucol[32 + lane] += t; }
        if (usedm & 4u) { float t = D - dj2;  v2 -= t; u[p2] += t; ucol[64 + lane] += t; }
        if (usedm & 8u) { float t = D - dj3;  v3 -= t; u[p3] += t; ucol[96 + lane] += t; }
        __syncwarp();

        while (j0 != 0) {
            int j1  = __shfl_sync(0xffffffffu, sel4i(w0, w1, w2, w3, j0 >> 5), j0 & 31);
            int pj1 = (j1 == 0) ? i : psh[j1];
            if ((j0 & 31) == lane) {
                int s = j0 >> 5;
                if (s == 0) p0 = pj1; else if (s == 1) p1 = pj1;
                else if (s == 2) p2 = pj1; else p3 = pj1;
                psh[j0] = pj1;
                ucol[j0] = u[pj1];
            }
            j0 = j1;
            __syncwarp();
        }
        __syncwarp();
    }

    // parallel emit
    int base = 0;
    #pragma unroll
    for (int c = 0; c < 4; ++c) {
        int j = c * 32 + lane + 1;
        bool m = (j <= NQ) && (psh[j] != 0);
        unsigned ball = __ballot_sync(0xffffffffu, m);
        if (m) {
            int k = base + __popc(ball & ((1u << lane) - 1u));
            out[b * NT + k]           = (float)(j - 1);
            out[NB * NT + b * NT + k] = (float)(psh[j] - 1);
        }
        base += __popc(ball);
    }
}

// ---------------- launch ----------------
extern "C" void kernel_launch(void* const* d_in, const int* in_sizes, int n_in,
                              void* d_out, int out_size) {
    const float* logits = nullptr;
    const float* pmask  = nullptr;
    const float* tmask  = nullptr;
    const int*   labels = nullptr;

    for (int i = 0; i < n_in; ++i) {
        switch (in_sizes[i]) {
            case 64800:    logits = (const float*)d_in[i]; break;
            case 52428800: pmask  = (const float*)d_in[i]; break;
            case 256:      labels = (const int*)d_in[i];   break;
            default:
                if (in_sizes[i] == 67108864) tmask = (const float*)d_in[i];
                break;
        }
    }
    float* out = (float*)d_out;

    k_class<<<NB * NQ, 32>>>(logits, labels);
    k_tmask<<<dim3(HW / 512, NB), 512>>>(tmask);
    k_main<<<dim3(8, 7, NB), 256>>>(pmask);
    k_hung<<<NB, 128>>>(out);
}

// round 17
// speedup vs baseline: 1.1854x; 1.0113x over previous
#include <cuda_runtime.h>
#include <cstdint>

#define HW    65536
#define NQ    100
#define NT    32
#define NB    8
#define NROWP 112   // 7 mtiles * 16
#define NKT   4096  // k-tiles per batch (HW/16)

// ---------------- device scratch ----------------
__device__ unsigned short g_bcomp[NB * NKT * 32]; // 16-bit B-operand codes (2MB)
__device__ float    g_tsum[NB * NT];
__device__ float    g_dotPM[NB * NROWP * NT];
__device__ float    g_dotSIG[NB * NROWP * NT];
__device__ float    g_sumSP[NB * NROWP];
__device__ float    g_sumSIG[NB * NROWP];
__device__ float    g_classT[NB * NT * NQ];      // [b][t][n]

// ---------------- helpers ----------------
__device__ __forceinline__ uint32_t pack_bf16(float hi, float lo) {
    uint32_t d;
    asm("cvt.rn.bf16x2.f32 %0, %1, %2;" : "=r"(d) : "f"(hi), "f"(lo));
    return d;
}

__device__ __forceinline__ void mma_bf16(float* c, const uint32_t* a,
                                         uint32_t b0, uint32_t b1) {
    asm volatile(
        "mma.sync.aligned.m16n8k16.row.col.f32.bf16.bf16.f32 "
        "{%0,%1,%2,%3}, {%4,%5,%6,%7}, {%8,%9}, {%0,%1,%2,%3};"
        : "+f"(c[0]), "+f"(c[1]), "+f"(c[2]), "+f"(c[3])
        : "r"(a[0]), "r"(a[1]), "r"(a[2]), "r"(a[3]), "r"(b0), "r"(b1));
}

__device__ __forceinline__ uint32_t fkey(float f) {
    uint32_t u = __float_as_uint(f);
    return (u & 0x80000000u) ? ~u : (u | 0x80000000u);
}
__device__ __forceinline__ float fkey_inv(uint32_t k) {
    uint32_t u = (k & 0x80000000u) ? (k ^ 0x80000000u) : ~k;
    return __uint_as_float(u);
}
__device__ __forceinline__ int sel4i(int a0, int a1, int a2, int a3, int s) {
    return s == 0 ? a0 : s == 1 ? a1 : s == 2 ? a2 : a3;
}

// gather bits {0,8,16,24} of x into nibble (carry-free multiply)
__device__ __forceinline__ uint32_t gath4(uint32_t x) {
    return (((x & 0x01010101u) * 0x01020408u) >> 24) & 0xFu;
}
// spread nibble bits j -> 4j
__device__ __forceinline__ uint32_t spr4(uint32_t n) {
    uint32_t a = (n | (n << 6)) & 0x0303u;
    return (a | (a << 3)) & 0x1111u;
}

// ---------------- kernel 1: class cost (+ accumulator zeroing) ----------------
__global__ void k_class(const float* __restrict__ logits,
                        const int* __restrict__ labels) {
    int gid = blockIdx.x * 32 + threadIdx.x;
    for (int i = gid; i < NB * NROWP * NT; i += NB * NQ * 32) {
        g_dotPM[i] = 0.f; g_dotSIG[i] = 0.f;
    }
    if (gid < NB * NROWP) { g_sumSP[gid] = 0.f; g_sumSIG[gid] = 0.f; }
    if (gid < NB * NT)    { g_tsum[gid] = 0.f; }

    int b = blockIdx.x / NQ, n = blockIdx.x % NQ;
    int lane = threadIdx.x;
    __shared__ float sh[81];
    const float* L = logits + (size_t)(b * NQ + n) * 81;

    float x0 = L[lane];
    float x1 = (lane + 32 < 81) ? L[lane + 32] : -1e30f;
    float x2 = (lane + 64 < 81) ? L[lane + 64] : -1e30f;
    float m = fmaxf(x0, fmaxf(x1, x2));
    #pragma unroll
    for (int o = 16; o; o >>= 1) m = fmaxf(m, __shfl_xor_sync(0xffffffffu, m, o));

    float e0 = __expf(x0 - m);
    float e1 = (lane + 32 < 81) ? __expf(x1 - m) : 0.f;
    float e2 = (lane + 64 < 81) ? __expf(x2 - m) : 0.f;
    float s = e0 + e1 + e2;
    #pragma unroll
    for (int o = 16; o; o >>= 1) s += __shfl_xor_sync(0xffffffffu, s, o);

    sh[lane] = e0;
    if (lane + 32 < 81) sh[lane + 32] = e1;
    if (lane + 64 < 81) sh[lane + 64] = e2;
    __syncwarp();

    float inv = 1.0f / s;
    int lbl = labels[b * NT + lane];
    g_classT[(b * NT + lane) * NQ + n] = -sh[lbl] * inv;
}

// ---------------- kernel 2: target masks -> sums + compact B codes ----------
__global__ __launch_bounds__(512) void k_tmask(const float* __restrict__ tgt) {
    __shared__ uint32_t slo[512];
    __shared__ uint32_t shi[512];
    const int b = blockIdx.y;
    const int tid = threadIdx.x;
    const int g = tid >> 8;
    const int px = tid & 255;
    const int lane = tid & 31;

    int p0 = blockIdx.x * 512 + px * 2;
    int h = p0 >> 8, w = p0 & 255;
    size_t base = ((size_t)(b * NT + g * 16)) * 262144 + (size_t)(2 * h) * 512 + 2 * w;
    uint32_t w0 = 0, w1 = 0;
    #pragma unroll
    for (int t = 0; t < 16; ++t) {
        float4 v = __ldcs((const float4*)(tgt + base + (size_t)t * 262144));
        w0 |= (uint32_t)(v.x != 0.0f) << (g * 16 + t);
        w1 |= (uint32_t)(v.z != 0.0f) << (g * 16 + t);
    }
    if (g == 0) { slo[px * 2] = w0; slo[px * 2 + 1] = w1; }
    else        { shi[px * 2] = w0; shi[px * 2 + 1] = w1; }
    __syncthreads();

    if (tid < 256) {
        uint32_t c0 = slo[tid * 2]     | shi[tid * 2];
        uint32_t c1 = slo[tid * 2 + 1] | shi[tid * 2 + 1];
        slo[tid * 2]     = c0;
        slo[tid * 2 + 1] = c1;
        int cnt = 0;
        #pragma unroll
        for (int t = 0; t < 32; ++t) {
            unsigned m0 = __ballot_sync(0xffffffffu, (c0 >> t) & 1u);
            unsigned m1 = __ballot_sync(0xffffffffu, (c1 >> t) & 1u);
            if (lane == t) cnt = __popc(m0) + __popc(m1);
        }
        atomicAdd(&g_tsum[b * NT + lane], (float)cnt);
    }
    __syncthreads();

    const int warp = tid >> 5;
    const int q4 = (lane & 3) << 2, rq = lane >> 2;
    #pragma unroll
    for (int i = 0; i < 2; ++i) {
        int ktl = warp * 2 + i;
        uint32_t t0 = slo[ktl * 16 + q4]     >> rq;
        uint32_t t1 = slo[ktl * 16 + q4 + 1] >> rq;
        uint32_t t2 = slo[ktl * 16 + q4 + 2] >> rq;
        uint32_t t3 = slo[ktl * 16 + q4 + 3] >> rq;
        uint32_t b16 = spr4(gath4(t0)) | (spr4(gath4(t1)) << 1)
                     | (spr4(gath4(t2)) << 2) | (spr4(gath4(t3)) << 3);
        int kt = blockIdx.x * 32 + ktl;
        g_bcomp[(size_t)(b * NKT + kt) * 32 + lane] = (unsigned short)b16;
    }
}

// ---------------- kernel 3: bf16x2 elementwise + MMA, compact-B expand ------
__global__ __launch_bounds__(256) void k_main(const float* __restrict__ pm) {
    __shared__ float sPM[16 * 32];
    __shared__ float sSG[16 * 32];
    __shared__ float sSP[16];
    __shared__ float sSS[16];

    const int b = blockIdx.z, mt = blockIdx.y;
    const int tid = threadIdx.x;
    const int warp = tid >> 5, lane = tid & 31;
    const int kstart = blockIdx.x * (HW / 8) + warp * (HW / 8 / 8);
    const int rq = lane >> 2;
    const int q4 = (lane & 3) << 2;
    const int kq = (lane & 3) << 1;
    const int r_lo = mt * 16 + rq, r_hi = r_lo + 8;
    const int rl = min(r_lo, NQ - 1), rh = min(r_hi, NQ - 1);

    for (int i = tid; i < 512; i += 256) { sPM[i] = 0.f; sSG[i] = 0.f; }
    if (tid < 16) { sSP[tid] = 0.f; sSS[tid] = 0.f; }
    __syncthreads();

    const float* pmb = pm + (size_t)b * NQ * HW;
    const unsigned short* bc = g_bcomp + (size_t)(b * NKT + (kstart >> 4)) * 32 + lane;

    const uint32_t HALF2  = 0x3F003F00u;
    const uint32_t NHALF2 = 0xBF00BF00u;
    const uint32_t ONES2  = 0x3F803F80u;

    float cpm[4][4], csg[4][4], csum[4];
    #pragma unroll
    for (int i = 0; i < 4; ++i) {
        csum[i] = 0.f;
        #pragma unroll
        for (int j = 0; j < 4; ++j) { cpm[i][j] = 0.f; csg[i][j] = 0.f; }
    }
    float splog0 = 0.f, splog1 = 0.f;

    #pragma unroll 4
    for (int it = 0; it < 64; ++it) {
        int k0 = kstart + it * 16 + q4;
        float4 xl = __ldcs((const float4*)(pmb + (size_t)rl * HW + k0));
        float4 xh = __ldcs((const float4*)(pmb + (size_t)rh * HW + k0));
        uint32_t b16 = bc[it * 32];

        uint32_t apm[4] = { pack_bf16(xl.y, xl.x), pack_bf16(xh.y, xh.x),
                            pack_bf16(xl.w, xl.z), pack_bf16(xh.w, xh.z) };

        uint32_t asg[4], aq[4];
        #pragma unroll
        for (int q = 0; q < 4; ++q) {
            uint32_t th;
            asm("mul.rn.bf16x2 %0, %1, %2;" : "=r"(th) : "r"(apm[q]), "r"(HALF2));
            asm("tanh.approx.bf16x2 %0, %1;" : "=r"(th) : "r"(th));
            asm("fma.rn.bf16x2 %0, %1, %2, %3;" : "=r"(asg[q]) : "r"(th), "r"(HALF2),  "r"(HALF2));
            asm("fma.rn.bf16x2 %0, %1, %2, %3;" : "=r"(aq[q])  : "r"(th), "r"(NHALF2), "r"(HALF2));
        }

        uint32_t prL, prH;
        asm("mul.rn.bf16x2 %0, %1, %2;" : "=r"(prL) : "r"(aq[0]), "r"(aq[2]));
        asm("mul.rn.bf16x2 %0, %1, %2;" : "=r"(prH) : "r"(aq[1]), "r"(aq[3]));
        float fL = __uint_as_float(prL << 16) * __uint_as_float(prL & 0xFFFF0000u);
        float fH = __uint_as_float(prH << 16) * __uint_as_float(prH & 0xFFFF0000u);
        splog0 += __logf(fL);
        splog1 += __logf(fH);

        #pragma unroll
        for (int nt = 0; nt < 4; ++nt) {
            uint32_t nib = (b16 >> (4 * nt)) & 0xFu;
            uint32_t bO0 = (nib & 1u) * 0x3F80u | ((nib >> 1) & 1u) * 0x3F800000u;
            uint32_t bO1 = ((nib >> 2) & 1u) * 0x3F80u | ((nib >> 3) & 1u) * 0x3F800000u;
            mma_bf16(cpm[nt], apm, bO0, bO1);
            mma_bf16(csg[nt], asg, bO0, bO1);
        }
        mma_bf16(csum, asg, ONES2, ONES2);
    }

    #pragma unroll
    for (int nt = 0; nt < 4; ++nt) {
        int c = nt * 8 + kq;
        atomicAdd(&sPM[rq * 32 + c],           cpm[nt][0]);
        atomicAdd(&sPM[rq * 32 + c + 1],       cpm[nt][1]);
        atomicAdd(&sPM[(rq + 8) * 32 + c],     cpm[nt][2]);
        atomicAdd(&sPM[(rq + 8) * 32 + c + 1], cpm[nt][3]);
        atomicAdd(&sSG[rq * 32 + c],           csg[nt][0]);
        atomicAdd(&sSG[rq * 32 + c + 1],       csg[nt][1]);
        atomicAdd(&sSG[(rq + 8) * 32 + c],     csg[nt][2]);
        atomicAdd(&sSG[(rq + 8) * 32 + c + 1], csg[nt][3]);
    }
    atomicAdd(&sSP[rq],     -splog0);
    atomicAdd(&sSP[rq + 8], -splog1);
    if (kq == 0) {
        atomicAdd(&sSS[rq],     csum[0]);
        atomicAdd(&sSS[rq + 8], csum[2]);
    }
    __syncthreads();

    for (int i = tid; i < 512; i += 256) {
        int r = i >> 5, c = i & 31;
        int grow = mt * 16 + r;
        atomicAdd(&g_dotPM[(b * NROWP + grow) * NT + c],  sPM[i]);
        atomicAdd(&g_dotSIG[(b * NROWP + grow) * NT + c], sSG[i]);
    }
    if (tid < 16) {
        int grow = mt * 16 + tid;
        atomicAdd(&g_sumSP[b * NROWP + grow],  sSP[tid]);
        atomicAdd(&g_sumSIG[b * NROWP + grow], sSS[tid]);
    }
}

// ---------------- kernel 4: cost assembly + JV (greedy + ARR + Dijkstra) ----
__global__ __launch_bounds__(128) void k_hung(float* __restrict__ out) {
    const int b = blockIdx.x;
    const int tid = threadIdx.x;
    const int lane = tid & 31;
    __shared__ float CsBuf[NT * NQ + 40];
    __shared__ float u[NT + 1];
    __shared__ float ucol[NQ + 1];
    __shared__ int   psh[NQ + 1];
    float* Cs = CsBuf + 1;

    for (int idx = tid; idx < NT * NQ; idx += 128) {
        int t = idx / NQ, n = idx - t * NQ;
        float spm  = g_sumSP[b * NROWP + n] * (1.0f / HW);
        float dpm  = g_dotPM[(b * NROWP + n) * NT + t] * (1.0f / HW);
        float dsg  = g_dotSIG[(b * NROWP + n) * NT + t];
        float den  = g_sumSIG[b * NROWP + n] + g_tsum[b * NT + t] + 1.0f;
        float dice = 1.0f - __fdividef(2.0f * dsg + 1.0f, den);
        Cs[idx] = g_classT[b * NT * NQ + idx] + (spm - dpm) + dice;
    }
    for (int j = tid; j <= NQ; j += 128) psh[j] = 0;
    __syncthreads();
    if (tid >= 32) return;

    float v0 = 0.f, v1 = 0.f, v2 = 0.f, v3 = 0.f;
    int   p0 = 0, p1 = 0, p2 = 0, p3 = 0;
    int   w0 = 0, w1 = 0, w2 = 0, w3 = 0;

    // ---- greedy init: row reduction + tight-arc matching ----
    uint32_t cm0 = 1u, cm1 = 0, cm2 = 0, cm3 = 0;
    uint32_t freerows = 0;
    for (int i = 1; i <= NT; ++i) {
        const float* Crow = Cs + (i - 1) * NQ;
        uint32_t k0 = (fkey(Crow[lane - 1]) & ~127u) | lane;
        k0 = (lane >= 1) ? k0 : 0xFFFFFFFFu;
        uint32_t k1 = (fkey(Crow[31 + lane]) & ~127u) | (32 + lane);
        uint32_t k2 = (fkey(Crow[63 + lane]) & ~127u) | (64 + lane);
        uint32_t k3 = (fkey(Crow[95 + lane]) & ~127u) | (96 + lane);
        k3 = (lane <= 4) ? k3 : 0xFFFFFFFFu;
        uint32_t bk = min(min(k0, k1), min(k2, k3));
        uint32_t kmin = __reduce_min_sync(0xffffffffu, bk);
        int js = kmin & 127;
        float ui = fkey_inv(kmin & ~127u);
        if (lane == 0) u[i] = ui;
        int slot = js >> 5;
        uint32_t bit = 1u << (js & 31);
        uint32_t cm = slot == 0 ? cm0 : slot == 1 ? cm1 : slot == 2 ? cm2 : cm3;
        if (!(cm & bit)) {
            if ((js & 31) == lane) {
                if (slot == 0) p0 = i; else if (slot == 1) p1 = i;
                else if (slot == 2) p2 = i; else p3 = i;
                psh[js] = i;
                ucol[js] = ui;
            }
            if (slot == 0) cm0 |= bit; else if (slot == 1) cm1 |= bit;
            else if (slot == 2) cm2 |= bit; else cm3 |= bit;
        } else {
            freerows |= 1u << (i - 1);
        }
    }
    __syncwarp();

    // ---- augmenting row reduction (LAPJV), 2 bounded passes ----
    #pragma unroll 1
    for (int pass = 0; pass < 2 && freerows; ++pass) {
        uint32_t next = 0;
        while (freerows) {
            int i = __ffs(freerows);
            freerows &= freerows - 1;
            const float* Crow = Cs + (i - 1) * NQ;

            uint32_t k0 = (fkey(Crow[lane - 1]  - v0) & ~127u) | lane;
            k0 = (lane >= 1) ? k0 : 0xFFFFFFFFu;
            uint32_t k1 = (fkey(Crow[31 + lane] - v1) & ~127u) | (32 + lane);
            uint32_t k2 = (fkey(Crow[63 + lane] - v2) & ~127u) | (64 + lane);
            uint32_t k3 = (fkey(Crow[95 + lane] - v3) & ~127u) | (96 + lane);
            k3 = (lane <= 4) ? k3 : 0xFFFFFFFFu;
            uint32_t bk = min(min(k0, k1), min(k2, k3));
            uint32_t kmin = __reduce_min_sync(0xffffffffu, bk);
            int j1 = kmin & 127;
            float m1 = fkey_inv(kmin & ~127u);
            int slot = j1 >> 5;

            // second min (exclude j1's slot on its owner lane)
            uint32_t bk2 = bk;
            if ((j1 & 31) == lane) {
                uint32_t x0 = (slot == 0) ? 0xFFFFFFFFu : k0;
                uint32_t x1 = (slot == 1) ? 0xFFFFFFFFu : k1;
                uint32_t x2 = (slot == 2) ? 0xFFFFFFFFu : k2;
                uint32_t x3 = (slot == 3) ? 0xFFFFFFFFu : k3;
                bk2 = min(min(x0, x1), min(x2, x3));
            }
            uint32_t k2min = __reduce_min_sync(0xffffffffu, bk2);
            float m2 = fkey_inv(k2min & ~127u);

            if (lane == 0) u[i] = m2;
            int owner = psh[j1];              // read before overwrite
            __syncwarp();
            if ((j1 & 31) == lane) {
                float dv = m2 - m1;           // >= 0 (quantized keys)
                if (slot == 0)      { v0 -= dv; p0 = i; }
                else if (slot == 1) { v1 -= dv; p1 = i; }
                else if (slot == 2) { v2 -= dv; p2 = i; }
                else                { v3 -= dv; p3 = i; }
                psh[j1]  = i;
                ucol[j1] = m2;
            }
            __syncwarp();
            if (owner) next |= 1u << (owner - 1);
        }
        freerows = next;
    }

    // ---- Dijkstra phases: branchless inner loop, lazy dual updates ----
    while (freerows) {
        int i = __ffs(freerows);
        freerows &= freerows - 1;
        float m0 = 1e30f, m1 = 1e30f, m2 = 1e30f, m3 = 1e30f;
        float dj0 = 0.f, dj1r = 0.f, dj2 = 0.f, dj3 = 0.f;
        float D = 0.f;
        unsigned usedm = 0;
        if (lane == 0) p0 = i;
        int j0 = 0, i0 = i;
        float ui0 = u[i];

        while (true) {
            unsigned joined = ((j0 & 31) == lane) ? (1u << (j0 >> 5)) : 0u;
            dj0  = (joined & 1u) ? D : dj0;
            dj1r = (joined & 2u) ? D : dj1r;
            dj2  = (joined & 4u) ? D : dj2;
            dj3  = (joined & 8u) ? D : dj3;
            usedm |= joined;

            const float* Cr = Cs + (i0 - 1) * NQ;
            float s0 = ui0 + v0, s1 = ui0 + v1, s2 = ui0 + v2, s3 = ui0 + v3;

            bool a0 = (lane >= 1) && !(usedm & 1u);
            bool a1 = !(usedm & 2u);
            bool a2 = !(usedm & 4u);
            bool a3 = (lane <= 4) && !(usedm & 8u);

            float c0 = Cr[lane - 1]  - s0;  c0 = a0 ? c0 : 1e30f;
            float c1 = Cr[31 + lane] - s1;  c1 = a1 ? c1 : 1e30f;
            float c2 = Cr[63 + lane] - s2;  c2 = a2 ? c2 : 1e30f;
            float c3 = Cr[95 + lane] - s3;  c3 = a3 ? c3 : 1e30f;

            bool b0 = c0 < m0; w0 = b0 ? j0 : w0; m0 = b0 ? c0 : m0;
            bool b1 = c1 < m1; w1 = b1 ? j0 : w1; m1 = b1 ? c1 : m1;
            bool b2 = c2 < m2; w2 = b2 ? j0 : w2; m2 = b2 ? c2 : m2;
            bool b3 = c3 < m3; w3 = b3 ? j0 : w3; m3 = b3 ? c3 : m3;

            uint32_t k0 = (fkey(m0) & ~127u) | lane;        k0 = a0 ? k0 : 0xFFFFFFFFu;
            uint32_t k1 = (fkey(m1) & ~127u) | (32 + lane); k1 = a1 ? k1 : 0xFFFFFFFFu;
            uint32_t k2 = (fkey(m2) & ~127u) | (64 + lane); k2 = a2 ? k2 : 0xFFFFFFFFu;
            uint32_t k3 = (fkey(m3) & ~127u) | (96 + lane); k3 = a3 ? k3 : 0xFFFFFFFFu;
            uint32_t bk = min(min(k0, k1), min(k2, k3));

            uint32_t kmin = __reduce_min_sync(0xffffffffu, bk);
            float delta = fkey_inv(kmin & ~127u);
            int j1 = kmin & 127;

            int   pj1 = psh[j1];
            float uc1 = ucol[j1];

            m0 -= (usedm & 1u) ? 0.f : delta;
            m1 -= (usedm & 2u) ? 0.f : delta;
            m2 -= (usedm & 4u) ? 0.f : delta;
            m3 -= (usedm & 8u) ? 0.f : delta;
            D += delta;

            j0 = j1;
            if (pj1 == 0) break;
            i0 = pj1;
            ui0 = uc1;
        }

        if (usedm & 1u) { float t = D - dj0;  v0 -= t; u[p0] += t; ucol[lane] += t; }
        if (usedm & 2u) { float t = D - dj1r; v1 -= t; u[p1] += t; ucol[32 + lane] += t; }
        if (usedm & 4u) { float t = D - dj2;  v2 -= t; u[p2] += t; ucol[64 + lane] += t; }
        if (usedm & 8u) { float t = D - dj3;  v3 -= t; u[p3] += t; ucol[96 + lane] += t; }
        __syncwarp();

        while (j0 != 0) {
            int j1  = __shfl_sync(0xffffffffu, sel4i(w0, w1, w2, w3, j0 >> 5), j0 & 31);
            int pj1 = (j1 == 0) ? i : psh[j1];
            if ((j0 & 31) == lane) {
                int s = j0 >> 5;
                if (s == 0) p0 = pj1; else if (s == 1) p1 = pj1;
                else if (s == 2) p2 = pj1; else p3 = pj1;
                psh[j0] = pj1;
                ucol[j0] = u[pj1];
            }
            j0 = j1;
            __syncwarp();
        }
        __syncwarp();
    }

    // parallel emit
    int base = 0;
    #pragma unroll
    for (int c = 0; c < 4; ++c) {
        int j = c * 32 + lane + 1;
        bool m = (j <= NQ) && (psh[j] != 0);
        unsigned ball = __ballot_sync(0xffffffffu, m);
        if (m) {
            int k = base + __popc(ball & ((1u << lane) - 1u));
            out[b * NT + k]           = (float)(j - 1);
            out[NB * NT + b * NT + k] = (float)(psh[j] - 1);
        }
        base += __popc(ball);
    }
}

// ---------------- launch ----------------
extern "C" void kernel_launch(void* const* d_in, const int* in_sizes, int n_in,
                              void* d_out, int out_size) {
    const float* logits = nullptr;
    const float* pmask  = nullptr;
    const float* tmask  = nullptr;
    const int*   labels = nullptr;

    for (int i = 0; i < n_in; ++i) {
        switch (in_sizes[i]) {
            case 64800:    logits = (const float*)d_in[i]; break;
            case 52428800: pmask  = (const float*)d_in[i]; break;
            case 256:      labels = (const int*)d_in[i];   break;
            default:
                if (in_sizes[i] == 67108864) tmask = (const float*)d_in[i];
                break;
        }
    }
    float* out = (float*)d_out;

    k_class<<<NB * NQ, 32>>>(logits, labels);
    k_tmask<<<dim3(HW / 512, NB), 512>>>(tmask);
    k_main<<<dim3(8, 7, NB), 256>>>(pmask);
    k_hung<<<NB, 128>>>(out);
}